// round 16
// baseline (speedup 1.0000x reference)
#include <cuda_runtime.h>
#include <cstdint>

// Fused y = conv3x3_same(x, w1); z = conv3x3_same(y, w2), [16,1,2048,2048] fp32.
// R15 structure (best: 100.8us) with the consume pipeline split so every
// latency is covered: raw LDS at step top (hidden under addY FMAs), shuffles
// mid-step (hidden under remaining addYs), packing at step end (inputs long
// ready; X's registers are dead by then). Warp = 256-col strip x 64-row chunk,
// 8 cols/lane, warp-private 6-slot cp.async smem ring, lane-local y-halo pair
// (shuffle-free fin). y forced to 0 outside the image.

#define IMG_H 2048
#define IMG_W 2048
#define ROWS 64
#define STRIPS 8
#define WARPS_PER_CTA 4
#define RING 6
#define ROWB 1088                  // 8 pad + 256 data + 8 pad floats
#define WSMEM (RING * ROWB)

typedef unsigned long long u64;

__device__ __forceinline__ u64 pk(float lo, float hi) {
    u64 r; asm("mov.b64 %0, {%1, %2};" : "=l"(r) : "f"(lo), "f"(hi)); return r;
}
__device__ __forceinline__ float lo32(u64 v) { return __uint_as_float((unsigned)v); }
__device__ __forceinline__ float hi32(u64 v) { return __uint_as_float((unsigned)(v >> 32)); }
__device__ __forceinline__ u64 fma2(u64 a, u64 b, u64 c) {
    u64 d; asm("fma.rn.f32x2 %0, %1, %2, %3;" : "=l"(d) : "l"(a), "l"(b), "l"(c)); return d;
}
__device__ __forceinline__ u64 mul2(u64 a, u64 b) {
    u64 d; asm("mul.rn.f32x2 %0, %1, %2;" : "=l"(d) : "l"(a), "l"(b)); return d;
}
__device__ __forceinline__ void cpa16(uint32_t d, const float* s) {
    asm volatile("cp.async.cg.shared.global [%0], [%1], 16;" :: "r"(d), "l"(s));
}
__device__ __forceinline__ void cpa8(uint32_t d, const float* s) {
    asm volatile("cp.async.ca.shared.global [%0], [%1], 8;" :: "r"(d), "l"(s));
}

struct RawQ { ulonglong2 A, B; float2 h; };   // one raw x row (per lane)
struct Shf  { float up7, dn0, up6, dn1; };    // halo shuffle results
struct XP   { u64 P[9]; u64 E[3]; };          // P[k]=(x[k-1],x[k]); E = edge pairs
struct YA   { u64 a[4]; u64 e; };             // e accumulates (y[-1], y[8])
struct YQ   { u64 Q[9]; };
struct ZA   { u64 a[4]; };

template <bool SAFE>
__device__ __forceinline__ void issue_row(char* slot, uint32_t slot_u,
                                          const float* src, int lane,
                                          bool lE, bool rE, bool inimg)
{
    if (SAFE || inimg) {
        uint32_t d = slot_u + 32 + lane * 32;
        cpa16(d,      src + 8 * lane);
        cpa16(d + 16, src + 8 * lane + 4);
        if (lane == 0  && !lE) cpa8(slot_u + 24,   src - 2);     // x[-2],x[-1]
        if (lane == 31 && !rE) cpa8(slot_u + 1056, src + 256);   // x[256],x[257]
    } else {
        float4 z4 = make_float4(0.f, 0.f, 0.f, 0.f);
        *(float4*)(slot + 32 + lane * 32) = z4;
        *(float4*)(slot + 48 + lane * 32) = z4;
        if (lane == 0)  *(float2*)(slot + 24)   = make_float2(0.f, 0.f);
        if (lane == 31) *(float2*)(slot + 1056) = make_float2(0.f, 0.f);
    }
}

// Raw loads only (2x LDS.128 + halo LDS.64). laneB = lane*32, hoffB precomputed.
__device__ __forceinline__ RawQ ldq(const char* slot, int laneB, int hoffB)
{
    RawQ q;
    const ulonglong2* dp = (const ulonglong2*)(slot + 32 + laneB);
    q.A = dp[0];
    q.B = dp[1];
    q.h = *(const float2*)(slot + hoffB);
    return q;
}

// Halo shuffles only.
__device__ __forceinline__ Shf shfq(const RawQ& q)
{
    Shf s;
    s.up7 = __shfl_up_sync(0xffffffffu, hi32(q.B.y), 1);
    s.dn0 = __shfl_down_sync(0xffffffffu, lo32(q.A.x), 1);
    s.up6 = __shfl_up_sync(0xffffffffu, lo32(q.B.y), 1);
    s.dn1 = __shfl_down_sync(0xffffffffu, hi32(q.A.x), 1);
    return s;
}

// Pack raw + shuffles into shifted f32x2 pairs (aligned pairs are free).
__device__ __forceinline__ XP packq(const RawQ& q, const Shf& s, int lane)
{
    float v0 = lo32(q.A.x), v1 = hi32(q.A.x);
    float v6 = lo32(q.B.y), v7 = hi32(q.B.y);
    float xm1 = (lane == 0)  ? q.h.y : s.up7;   // x[8g-1]
    float xp8 = (lane == 31) ? q.h.x : s.dn0;   // x[8g+8]
    float xm2 = (lane == 0)  ? q.h.x : s.up6;   // x[8g-2]
    float xp9 = (lane == 31) ? q.h.y : s.dn1;   // x[8g+9]
    XP x;
    x.P[0] = pk(xm1, v0);
    x.P[1] = q.A.x;
    x.P[2] = pk(v1, lo32(q.A.y));
    x.P[3] = q.A.y;
    x.P[4] = pk(hi32(q.A.y), lo32(q.B.x));
    x.P[5] = q.B.x;
    x.P[6] = pk(hi32(q.B.x), v6);
    x.P[7] = q.B.y;
    x.P[8] = pk(v7, xp8);
    x.E[0] = pk(xm2, v7);
    x.E[1] = pk(xm1, xp8);
    x.E[2] = pk(v0,  xp9);
    return x;
}

template <int A, bool FIRST>
__device__ __forceinline__ void addY(YA& y, const XP& x, const u64* W)
{
#pragma unroll
    for (int j = 0; j < 4; j++) {
        u64 t = FIRST ? mul2(W[3*A], x.P[2*j])
                      : fma2(W[3*A], x.P[2*j], y.a[j]);
        t = fma2(W[3*A+1], x.P[2*j+1], t);
        y.a[j] = fma2(W[3*A+2], x.P[2*j+2], t);
    }
    u64 e = FIRST ? mul2(W[3*A], x.E[0])
                  : fma2(W[3*A], x.E[0], y.e);
    e = fma2(W[3*A+1], x.E[1], e);
    y.e = fma2(W[3*A+2], x.E[2], e);
}

// Shuffle-free fin: halo y values are the lane-local pair y.e.
template <bool SAFE>
__device__ __forceinline__ YQ fin(YA y, bool valid, bool kL, bool kR)
{
    if (!SAFE && !valid) {
#pragma unroll
        for (int j = 0; j < 4; j++) y.a[j] = 0ull;
        y.e = 0ull;
    }
    float ym1 = lo32(y.e);
    float yp8 = hi32(y.e);
    if (kL) ym1 = 0.f;
    if (kR) yp8 = 0.f;
    YQ q;
    q.Q[0] = pk(ym1, lo32(y.a[0]));
#pragma unroll
    for (int j = 0; j < 4; j++) q.Q[2*j+1] = y.a[j];
#pragma unroll
    for (int j = 1; j < 4; j++) q.Q[2*j] = pk(hi32(y.a[j-1]), lo32(y.a[j]));
    q.Q[8] = pk(hi32(y.a[3]), yp8);
    return q;
}

template <int A, bool FIRST>
__device__ __forceinline__ void addZ(ZA& z, const YQ& q, const u64* W)
{
#pragma unroll
    for (int j = 0; j < 4; j++) {
        u64 t = FIRST ? mul2(W[3*A], q.Q[2*j])
                      : fma2(W[3*A], q.Q[2*j], z.a[j]);
        t = fma2(W[3*A+1], q.Q[2*j+1], t);
        z.a[j] = fma2(W[3*A+2], q.Q[2*j+2], t);
    }
}

__device__ __forceinline__ void stz(float* p, const ZA& z)
{
    *(float4*)p       = make_float4(lo32(z.a[0]), hi32(z.a[0]),
                                    lo32(z.a[1]), hi32(z.a[1]));
    *(float4*)(p + 4) = make_float4(lo32(z.a[2]), hi32(z.a[2]),
                                    lo32(z.a[3]), hi32(z.a[3]));
}

template <bool SAFE>
__device__ __forceinline__ void run(char* wb, uint32_t wb_u,
                                    const float* __restrict__ xb,
                                    float* __restrict__ ob,
                                    const float* __restrict__ w1g,
                                    const float* __restrict__ w2g,
                                    int c0, int R0, int lane, bool lE, bool rE)
{
    u64 W1[9], W2[9];
#pragma unroll
    for (int i = 0; i < 9; i++) {
        float a = __ldg(w1g + i); W1[i] = pk(a, a);
        float b = __ldg(w2g + i); W2[i] = pk(b, b);
    }
    const bool kL = (lane == 0  && lE);
    const bool kR = (lane == 31 && rE);
    const int laneB = lane * 32;
    const int hoffB = (lane == 31) ? 1056 : 24;

    // Zero halo pads once (read only by the lane that zeroes them).
    if (lane == 0) {
#pragma unroll
        for (int s = 0; s < RING; s++)
            *(float2*)(wb + s * ROWB + 24) = make_float2(0.f, 0.f);
    }
    if (lane == 31) {
#pragma unroll
        for (int s = 0; s < RING; s++)
            *(float2*)(wb + s * ROWB + 1056) = make_float2(0.f, 0.f);
    }

    // ---- Prologue: issue rows R0-2 .. R0+2 into slots 0..4 ----
    const float* srcp = xb + (size_t)(R0 - 2) * IMG_W + c0;
    int irow = R0 - 2;
    const int RLAST = R0 + 65;
#pragma unroll
    for (int s = 0; s < 5; s++) {
        issue_row<SAFE>(wb + s * ROWB, wb_u + s * ROWB, srcp, lane, lE, rE,
                        (unsigned)irow < IMG_H);
        asm volatile("cp.async.commit_group;");
        srcp += IMG_W; irow++;
    }

    int coff = 0;
    float* orow = ob + (size_t)R0 * IMG_W + c0 + 8 * lane;
    int r = R0;

    // Prologue-style consume: full chain in one go (outside the hot loop).
#define CONSUME(XV)                                                           \
    do {                                                                      \
        asm volatile("cp.async.wait_group 4;");                               \
        RawQ Qr_ = ldq(wb + coff, laneB, hoffB);                              \
        Shf  Sh_ = shfq(Qr_);                                                 \
        XV = packq(Qr_, Sh_, lane);                                           \
        int io_ = coff + 5 * ROWB; if (io_ >= WSMEM) io_ -= WSMEM;            \
        coff += ROWB; if (coff == WSMEM) coff = 0;                            \
        if (irow <= RLAST) {                                                  \
            issue_row<SAFE>(wb + io_, wb_u + io_, srcp, lane, lE, rE,         \
                            (unsigned)irow < IMG_H);                          \
            srcp += IMG_W; irow++;                                            \
        }                                                                     \
        asm volatile("cp.async.commit_group;");                               \
    } while (0)

    YA t1, t2, ya, yb, yc;
    ZA za, zb, zc;

    XP A; CONSUME(A);                                  // row R0-2
    addY<0, true >(t1, A, W1);
    XP B; CONSUME(B);                                  // row R0-1
    addY<1, false>(t1, B, W1);
    addY<0, true >(t2, B, W1);
    XP C; CONSUME(C);                                  // row R0
    addY<2, false>(t1, C, W1);
    addY<1, false>(t2, C, W1);
    addY<0, true >(ya, C, W1);
    YQ Q = fin<SAFE>(t1, (unsigned)(R0 - 1) < IMG_H, kL, kR);
    addZ<0, true >(za, Q, W2);
    XP D; CONSUME(D);                                  // row R0+1
    addY<2, false>(t2, D, W1);
    addY<1, false>(ya, D, W1);
    addY<0, true >(yb, D, W1);
    Q = fin<SAFE>(t2, true, kL, kR);
    addZ<1, false>(za, Q, W2);
    addZ<0, true >(zb, Q, W2);

    XP X; CONSUME(X);                                  // row R0+2 (primes pipeline)

    // ---- Steady state, latency-split:
    //   top:    wait + raw LDS of row r+3  (29cy hidden under addY block)
    //   mid:    halo shuffles               (26cy hidden under remaining addYs)
    //   late:   issue next row, fin/addZ/store
    //   end:    pack raw -> X for next step (inputs long ready) ----
#define STEP(Y0, Y1, Y2, Z0, Z1, Z2)                                          \
    do {                                                                      \
        asm volatile("cp.async.wait_group 4;");                               \
        RawQ Qr = ldq(wb + coff, laneB, hoffB);                               \
        addY<2, false>(Y0, X, W1);                                            \
        Shf Sh = shfq(Qr);                                                    \
        addY<1, false>(Y1, X, W1);                                            \
        addY<0, true >(Y2, X, W1);                                            \
        {                                                                     \
            int io_ = coff + 5 * ROWB; if (io_ >= WSMEM) io_ -= WSMEM;        \
            coff += ROWB; if (coff == WSMEM) coff = 0;                        \
            if (irow <= RLAST) {                                              \
                issue_row<SAFE>(wb + io_, wb_u + io_, srcp, lane, lE, rE,     \
                                (unsigned)irow < IMG_H);                      \
                srcp += IMG_W; irow++;                                        \
            }                                                                 \
            asm volatile("cp.async.commit_group;");                           \
        }                                                                     \
        YQ Qs = fin<SAFE>(Y0, (unsigned)(r + 1) < IMG_H, kL, kR);             \
        addZ<2, false>(Z0, Qs, W2);                                           \
        addZ<1, false>(Z1, Qs, W2);                                           \
        addZ<0, true >(Z2, Qs, W2);                                           \
        stz(orow, Z0);                                                        \
        X = packq(Qr, Sh, lane);                                              \
        orow += IMG_W; r++;                                                   \
    } while (0)

#define STEPNL(Y0, Y1, Y2, Z0, Z1, Z2)                                        \
    do {                                                                      \
        addY<2, false>(Y0, X, W1);                                            \
        addY<1, false>(Y1, X, W1);                                            \
        addY<0, true >(Y2, X, W1);                                            \
        YQ Qs = fin<SAFE>(Y0, (unsigned)(r + 1) < IMG_H, kL, kR);             \
        addZ<2, false>(Z0, Qs, W2);                                           \
        addZ<1, false>(Z1, Qs, W2);                                           \
        addZ<0, true >(Z2, Qs, W2);                                           \
        stz(orow, Z0);                                                        \
        orow += IMG_W; r++;                                                   \
    } while (0)

#pragma unroll 1
    for (int i = 0; i < 21; i++) {                     // 63 rows
        STEP(ya, yb, yc, za, zb, zc);
        STEP(yb, yc, ya, zb, zc, za);
        STEP(yc, ya, yb, zc, za, zb);
    }
    STEPNL(ya, yb, yc, za, zb, zc);                    // row 64 (X already held)
#undef STEP
#undef STEPNL
#undef CONSUME
}

__global__ __launch_bounds__(WARPS_PER_CTA * 32, 4)
void conv2x_ring6(const float* __restrict__ x, const float* __restrict__ w1g,
                  const float* __restrict__ w2g, float* __restrict__ out)
{
    __shared__ __align__(16) char smem[WARPS_PER_CTA * WSMEM];   // 26112 B

    const int lane  = threadIdx.x & 31;
    const int wrp   = threadIdx.x >> 5;
    const int strip = blockIdx.x;                       // 0..7
    const int chunk = blockIdx.y * WARPS_PER_CTA + wrp; // 0..31
    const int c0 = strip * 256;
    const int R0 = chunk * ROWS;
    const bool lE = (strip == 0);
    const bool rE = (strip == STRIPS - 1);

    char* wb = smem + wrp * WSMEM;
    uint32_t wb_u = (uint32_t)__cvta_generic_to_shared(wb);

    const float* xb = x   + (size_t)blockIdx.z * ((size_t)IMG_H * IMG_W);
    float*       ob = out + (size_t)blockIdx.z * ((size_t)IMG_H * IMG_W);

    if (chunk != 0 && chunk != (IMG_H / ROWS) - 1)
        run<true >(wb, wb_u, xb, ob, w1g, w2g, c0, R0, lane, lE, rE);
    else
        run<false>(wb, wb_u, xb, ob, w1g, w2g, c0, R0, lane, lE, rE);
}

extern "C" void kernel_launch(void* const* d_in, const int* in_sizes, int n_in,
                              void* d_out, int out_size)
{
    const float* x  = (const float*)d_in[0];
    const float* w1 = (const float*)d_in[1];
    const float* w2 = (const float*)d_in[2];
    float* out = (float*)d_out;

    cudaFuncSetAttribute(conv2x_ring6,
                         cudaFuncAttributePreferredSharedMemoryCarveout, 100);

    const int B = in_sizes[0] / (IMG_H * IMG_W);            // 16
    dim3 grid(STRIPS, (IMG_H / ROWS) / WARPS_PER_CTA, B);   // 8 x 8 x 16 = 1024
    conv2x_ring6<<<grid, WARPS_PER_CTA * 32>>>(x, w1, w2, out);
}